// round 8
// baseline (speedup 1.0000x reference)
#include <cuda_runtime.h>
#include <math.h>

// ---------------------------------------------------------------------------
// FIRE bias: out[h,s,t] = b2[h] + sum_w w2[h,w] * relu(w1[w]*nd(s,t) + b1[w])
// nd(s,t) = log((|s-t|+EPS)*c + 1+EPS) / log(|c*(max(s,thr)+EPS)| + 1+EPS)
//
// One persistent-wave kernel. Each block builds the piecewise-affine form of
// the MLP once (sorted breakpoints -b1/w1; per-interval (A,C) built from
// PARALLEL per-step deltas + a short 12-thread prefix scan), then grid-strides
// over (row, 1024-col chunk) units streaming float4 __stcs stores.
// Grid = 8 blocks/SM * numSMs -> setup amortized over ~3.5 units/block and
// fully overlapped across the single wave. HBM-write-bound target ~6 TB/s.
// ---------------------------------------------------------------------------

#define FIRE_EPS 1e-6f
#define FIRE_LOG_BIAS 1.0f

template <int H, int W>
__global__ void __launch_bounds__(256, 8) fire_fused(
    float* __restrict__ out,
    const float* __restrict__ w1, const float* __restrict__ b1,
    const float* __restrict__ w2, const float* __restrict__ b2,
    const float* __restrict__ cp, const float* __restrict__ Lm,
    const float* __restrict__ iL, int S) {

    __shared__ float shT[W];                 // sorted breakpoints (+inf for sl==0)
    __shared__ float shA[(W + 1) * H];       // per-interval slope per head
    __shared__ float shC[(W + 1) * H];       // per-interval offset per head
    __shared__ float s_sl[W], s_b1[W], s_traw[W];
    __shared__ int   s_unit[W];              // sorted position -> unit index
    __shared__ float s_dA[W * H], s_dC[W * H];  // per sorted-step toggle deltas
    __shared__ float s_w2[H * W];
    __shared__ float s_scal[2];              // c, thr

    const int tid = threadIdx.x;

    // ---- per-block setup, parallelized ----
    if (tid < W) {
        float sl = __ldg(w1 + tid);
        float bb = __ldg(b1 + tid);
        s_sl[tid] = sl;
        s_b1[tid] = bb;
        s_traw[tid] = (sl != 0.0f) ? (-bb / sl) : __int_as_float(0x7f800000);
    }
    if (tid == 0) {
        float c = __ldg(cp);
        s_scal[0] = c;
        s_scal[1] = fabsf(__ldg(Lm) * __ldg(iL));
    }
    for (int k = tid; k < H * W; k += blockDim.x) s_w2[k] = __ldg(w2 + k);
    __syncthreads();

    if (tid < W) {  // rank sort with index tie-break
        float tw = s_traw[tid];
        int r = 0;
        for (int v = 0; v < W; ++v) {
            float tv = s_traw[v];
            if (tv < tw || (tv == tw && v < tid)) r++;
        }
        shT[r] = tw;
        s_unit[r] = tid;
    }
    __syncthreads();

    // parallel toggle deltas: crossing sorted breakpoint r toggles unit u.
    // sl>0 activates (+), sl<0 deactivates (-), sl==0 never toggles.
    for (int k = tid; k < W * H; k += blockDim.x) {
        int r = k / H;
        int h = k - r * H;
        int u = s_unit[r];
        float sl = s_sl[u];
        float ww = s_w2[h * W + u];
        float dA = 0.0f, dC = 0.0f;
        if (sl > 0.0f)      { dA = ww * sl;  dC = ww * s_b1[u]; }
        else if (sl < 0.0f) { dA = -ww * sl; dC = -ww * s_b1[u]; }
        s_dA[k] = dA;
        s_dC[k] = dC;
    }
    __syncthreads();

    if (tid < H) {  // short prefix scan, one thread per head
        const int h = tid;
        float A = 0.0f;
        float Cc = __ldg(b2 + h);
        // interval 0: active iff sl<0 (or sl==0 && b1>0 -> constant term)
        for (int w = 0; w < W; ++w) {
            float sl = s_sl[w];
            if ((sl < 0.0f) || (sl == 0.0f && s_b1[w] > 0.0f)) {
                float ww = s_w2[h * W + w];
                A  = fmaf(ww, sl, A);
                Cc = fmaf(ww, s_b1[w], Cc);
            }
        }
        shA[h] = A;
        shC[h] = Cc;
        for (int i = 1; i <= W; ++i) {
            A  += s_dA[(i - 1) * H + h];
            Cc += s_dC[(i - 1) * H + h];
            shA[i * H + h] = A;
            shC[i * H + h] = Cc;
        }
    }
    __syncthreads();

    const float c   = s_scal[0];
    const float thr = s_scal[1];
    const size_t plane = (size_t)S * (size_t)S;

    // ---- persistent streaming loop over (row, chunk) units ----
    const int chunkElems = blockDim.x * 4;                 // 1024
    const int chunksPerRow = (S + chunkElems - 1) / chunkElems;
    const int nUnits = S * chunksPerRow;

    for (int u = blockIdx.x; u < nUnits; u += gridDim.x) {
        const int s = u / chunksPerRow;
        const int t0 = (u - s * chunksPerRow) * chunkElems + tid * 4;

        const float posn = fmaxf((float)s, thr) + FIRE_EPS;
        const float invln = __fdividef(1.0f, __logf(fabsf(c * posn) + FIRE_LOG_BIAS + FIRE_EPS));
        const size_t rowbase = (size_t)s * (size_t)S;

        if (t0 + 3 < S) {
            float nd[4];
#pragma unroll
            for (int e = 0; e < 4; ++e) {
                int t = t0 + e;
                int d = (s >= t) ? (s - t) : (t - s);
                nd[e] = __logf(fmaf((float)d + FIRE_EPS, c, FIRE_LOG_BIAS + FIRE_EPS)) * invln;
            }
            float ndmin = fminf(fminf(nd[0], nd[1]), fminf(nd[2], nd[3]));
            float ndmax = fmaxf(fmaxf(nd[0], nd[1]), fmaxf(nd[2], nd[3]));

            // lower_bound: i = #{shT[k] < v}
            int lo = 0, hi = W;
            while (lo < hi) { int m = (lo + hi) >> 1; if (shT[m] < ndmin) lo = m + 1; else hi = m; }
            int imin = lo;
            lo = imin; hi = W;
            while (lo < hi) { int m = (lo + hi) >> 1; if (shT[m] < ndmax) lo = m + 1; else hi = m; }
            int imax = lo;

            size_t base = rowbase + (size_t)t0;
            if (imin == imax) {
                int r = imin * H;
#pragma unroll
                for (int h = 0; h < H; ++h) {
                    float a = shA[r + h];
                    float cc = shC[r + h];
                    float4 v;
                    v.x = fmaf(a, nd[0], cc);
                    v.y = fmaf(a, nd[1], cc);
                    v.z = fmaf(a, nd[2], cc);
                    v.w = fmaf(a, nd[3], cc);
                    __stcs(reinterpret_cast<float4*>(out + (size_t)h * plane + base), v);
                }
            } else {
                int row[4];
#pragma unroll
                for (int e = 0; e < 4; ++e) {
                    float v = nd[e];
                    int l = imin, hh = imax;
                    while (l < hh) { int m = (l + hh) >> 1; if (shT[m] < v) l = m + 1; else hh = m; }
                    row[e] = l * H;
                }
#pragma unroll
                for (int h = 0; h < H; ++h) {
                    float4 v;
                    v.x = fmaf(shA[row[0] + h], nd[0], shC[row[0] + h]);
                    v.y = fmaf(shA[row[1] + h], nd[1], shC[row[1] + h]);
                    v.z = fmaf(shA[row[2] + h], nd[2], shC[row[2] + h]);
                    v.w = fmaf(shA[row[3] + h], nd[3], shC[row[3] + h]);
                    __stcs(reinterpret_cast<float4*>(out + (size_t)h * plane + base), v);
                }
            }
        } else {
            // scalar tail (unused when S % 1024 == 0)
            for (int t = t0; t < S && t < t0 + 4; ++t) {
                int d = (s >= t) ? (s - t) : (t - s);
                float v = __logf(fmaf((float)d + FIRE_EPS, c, FIRE_LOG_BIAS + FIRE_EPS)) * invln;
                int lo = 0, hi = W;
                while (lo < hi) { int m = (lo + hi) >> 1; if (shT[m] < v) lo = m + 1; else hi = m; }
                for (int h = 0; h < H; ++h)
                    out[(size_t)h * plane + rowbase + t] = fmaf(shA[lo * H + h], v, shC[lo * H + h]);
            }
        }
    }
}

// ---- generic fallback (runtime H, W) -------------------------------------
__global__ void fire_generic(const float* __restrict__ w1, const float* __restrict__ b1,
                             const float* __restrict__ w2, const float* __restrict__ b2,
                             const float* __restrict__ cp, const float* __restrict__ Lm,
                             const float* __restrict__ iL,
                             float* __restrict__ out, int S, int W, int H) {
    int s = blockIdx.y;
    int t = blockIdx.x * blockDim.x + threadIdx.x;
    if (t >= S) return;
    float c = cp[0];
    float thr = fabsf(Lm[0] * iL[0]);
    int d = (s >= t) ? (s - t) : (t - s);
    float log_rel = logf(fmaf((float)d + FIRE_EPS, c, FIRE_LOG_BIAS + FIRE_EPS));
    float posn = fmaxf((float)s, thr) + FIRE_EPS;
    float nd = log_rel / logf(fabsf(c * posn) + FIRE_LOG_BIAS + FIRE_EPS);
    for (int h = 0; h < H; ++h) {
        float acc = b2[h];
        for (int w = 0; w < W; ++w) {
            float hv = fmaf(w1[w], nd, b1[w]);
            hv = fmaxf(hv, 0.0f);
            acc = fmaf(w2[h * W + w], hv, acc);
        }
        out[(size_t)h * S * S + (size_t)s * S + t] = acc;
    }
}

extern "C" void kernel_launch(void* const* d_in, const int* in_sizes, int n_in,
                              void* d_out, int out_size) {
    // inputs: x, w1, b1, w2, b2, c, L_multiplier, init_L  (x unused by the math)
    const float* w1 = (const float*)d_in[1];
    const float* b1 = (const float*)d_in[2];
    const float* w2 = (const float*)d_in[3];
    const float* b2 = (const float*)d_in[4];
    const float* c  = (const float*)d_in[5];
    const float* Lm = (const float*)d_in[6];
    const float* iL = (const float*)d_in[7];

    int W = in_sizes[1];          // w1 is (W,1)
    int H = in_sizes[4];          // b2 is (H,)
    long long ss = (long long)out_size / (long long)H;  // S*S
    int S = (int)(sqrt((double)ss) + 0.5);

    if (H == 12 && W == 32) {
        int numSMs = 148;
        cudaDeviceGetAttribute(&numSMs, cudaDevAttrMultiProcessorCount, 0);
        int grid = numSMs * 8;    // one full wave at 8 blocks/SM
        fire_fused<12, 32><<<grid, 256>>>((float*)d_out, w1, b1, w2, b2, c, Lm, iL, S);
    } else {
        dim3 block(256);
        dim3 grid((unsigned)((S + 255) / 256), (unsigned)S);
        fire_generic<<<grid, block>>>(w1, b1, w2, b2, c, Lm, iL, (float*)d_out, S, W, H);
    }
}

// round 9
// speedup vs baseline: 1.3488x; 1.3488x over previous
#include <cuda_runtime.h>
#include <math.h>

// ---------------------------------------------------------------------------
// FIRE bias: out[h,s,t] = b2[h] + sum_w w2[h,w] * relu(w1[w]*nd(s,t) + b1[w])
// nd(s,t) = logrel[|s-t|] * invlognorm[s]  (two 1-D L1-resident tables)
// MLP is piecewise-affine in nd: bias_h = A[i][h]*nd + C[i][h] over <=W+1
// intervals (sorted breakpoints -b1/w1).
//
// Two kernels: (1) one small setup kernel building tables (8 blocks) and
// breakpoints+coefficients (block 0) — all independent writes, no cross-block
// deps; (2) the measured-best streaming kernel (R1 shape, 33.2us): table
// lookup, interval search shared across 4 elems, 12 FMAs/elem, float4 __stcs.
// Fused-MUFU variants measured 58-63us (latency-bound chain) — do not revisit.
// ---------------------------------------------------------------------------

#define FIRE_EPS 1e-6f
#define FIRE_LOG_BIAS 1.0f
#define MAX_S 4096
#define MAX_W 64
#define MAX_H 16

__device__ float g_logrel[MAX_S];
__device__ float g_invlognorm[MAX_S];
__device__ float g_sortedT[MAX_W];
__device__ float g_A[(MAX_W + 1) * MAX_H];
__device__ float g_C[(MAX_W + 1) * MAX_H];

// ---- single setup kernel: grid 8 x 256 ----------------------------------
__global__ void fire_setup(const float* __restrict__ w1, const float* __restrict__ b1,
                           const float* __restrict__ w2, const float* __restrict__ b2,
                           const float* __restrict__ cp, const float* __restrict__ Lm,
                           const float* __restrict__ iL, int S, int W, int H) {
    const int tid = threadIdx.x;
    const float c = __ldg(cp);
    const float thr = fabsf(__ldg(Lm) * __ldg(iL));

    // 1-D tables, split across all blocks (one logf per thread at S=2048)
    for (int s = blockIdx.x * blockDim.x + tid; s < S; s += gridDim.x * blockDim.x) {
        float absrel = (float)s + FIRE_EPS;
        g_logrel[s] = logf(fmaf(absrel, c, FIRE_LOG_BIAS + FIRE_EPS));
        float posn = fmaxf((float)s, thr) + FIRE_EPS;
        g_invlognorm[s] = 1.0f / logf(fabsf(c * posn) + FIRE_LOG_BIAS + FIRE_EPS);
    }

    // block 0 additionally builds breakpoints + per-interval coefficients
    if (blockIdx.x != 0) return;

    __shared__ float s_t[MAX_W], s_sl[MAX_W], s_b1[MAX_W];
    __shared__ int s_rank[MAX_W];
    if (tid < W) {
        float sl = __ldg(w1 + tid);
        float bb = __ldg(b1 + tid);
        s_sl[tid] = sl;
        s_b1[tid] = bb;
        s_t[tid] = (sl != 0.0f) ? (-bb / sl) : __int_as_float(0x7f800000);
    }
    __syncthreads();
    if (tid < W) {  // rank sort, index tie-break
        float tw = s_t[tid];
        int r = 0;
        for (int v = 0; v < W; ++v) {
            float tv = s_t[v];
            if (tv < tw || (tv == tw && v < tid)) r++;
        }
        s_rank[tid] = r;
        g_sortedT[r] = tw;
    }
    __syncthreads();
    // interval i = #{sorted breakpoints < nd}; each (i,h) entry independent
    for (int k = tid; k < (W + 1) * H; k += blockDim.x) {
        int i = k / H;
        int h = k - i * H;
        float Asum = 0.0f;
        float Csum = __ldg(b2 + h);
        for (int w = 0; w < W; ++w) {
            float sl = s_sl[w];
            bool active;
            if (sl > 0.0f)      active = (i > s_rank[w]);
            else if (sl < 0.0f) active = (i <= s_rank[w]);
            else                active = (s_b1[w] > 0.0f);
            if (active) {
                float ww = __ldg(w2 + h * W + w);
                Asum = fmaf(ww, sl, Asum);
                Csum = fmaf(ww, s_b1[w], Csum);
            }
        }
        g_A[k] = Asum;
        g_C[k] = Csum;
    }
}

// ---- main streaming kernel (measured-best shape) -------------------------
template <int H, int W>
__global__ void __launch_bounds__(256) fire_main(float* __restrict__ out, int S) {
    __shared__ float shT[W];
    __shared__ float shA[(W + 1) * H];
    __shared__ float shC[(W + 1) * H];

    for (int k = threadIdx.x; k < W; k += blockDim.x) shT[k] = g_sortedT[k];
    for (int k = threadIdx.x; k < (W + 1) * H; k += blockDim.x) {
        shA[k] = g_A[k];
        shC[k] = g_C[k];
    }
    __syncthreads();

    const int s = blockIdx.y;
    const int t0 = (blockIdx.x * blockDim.x + threadIdx.x) * 4;
    if (t0 >= S) return;

    const float invln = __ldg(&g_invlognorm[s]);
    const size_t plane = (size_t)S * (size_t)S;
    const size_t rowbase = (size_t)s * (size_t)S;

    if (t0 + 3 < S) {
        float nd[4];
#pragma unroll
        for (int e = 0; e < 4; ++e) {
            int t = t0 + e;
            int d = (s >= t) ? (s - t) : (t - s);
            nd[e] = __ldg(&g_logrel[d]) * invln;
        }
        float ndmin = fminf(fminf(nd[0], nd[1]), fminf(nd[2], nd[3]));
        float ndmax = fmaxf(fmaxf(nd[0], nd[1]), fmaxf(nd[2], nd[3]));

        // lower_bound: i = #{shT[k] < v}
        int lo = 0, hi = W;
        while (lo < hi) { int m = (lo + hi) >> 1; if (shT[m] < ndmin) lo = m + 1; else hi = m; }
        int imin = lo;
        lo = imin; hi = W;
        while (lo < hi) { int m = (lo + hi) >> 1; if (shT[m] < ndmax) lo = m + 1; else hi = m; }
        int imax = lo;

        size_t base = rowbase + (size_t)t0;
        if (imin == imax) {
            int r = imin * H;
#pragma unroll
            for (int h = 0; h < H; ++h) {
                float a = shA[r + h];
                float cc = shC[r + h];
                float4 v;
                v.x = fmaf(a, nd[0], cc);
                v.y = fmaf(a, nd[1], cc);
                v.z = fmaf(a, nd[2], cc);
                v.w = fmaf(a, nd[3], cc);
                __stcs(reinterpret_cast<float4*>(out + (size_t)h * plane + base), v);
            }
        } else {
            int row[4];
#pragma unroll
            for (int e = 0; e < 4; ++e) {
                float v = nd[e];
                int l = imin, hh = imax;
                while (l < hh) { int m = (l + hh) >> 1; if (shT[m] < v) l = m + 1; else hh = m; }
                row[e] = l * H;
            }
#pragma unroll
            for (int h = 0; h < H; ++h) {
                float4 v;
                v.x = fmaf(shA[row[0] + h], nd[0], shC[row[0] + h]);
                v.y = fmaf(shA[row[1] + h], nd[1], shC[row[1] + h]);
                v.z = fmaf(shA[row[2] + h], nd[2], shC[row[2] + h]);
                v.w = fmaf(shA[row[3] + h], nd[3], shC[row[3] + h]);
                __stcs(reinterpret_cast<float4*>(out + (size_t)h * plane + base), v);
            }
        }
    } else {
        // scalar tail (unused when S % 4 == 0)
        for (int t = t0; t < S; ++t) {
            int d = (s >= t) ? (s - t) : (t - s);
            float v = __ldg(&g_logrel[d]) * invln;
            int lo = 0, hi = W;
            while (lo < hi) { int m = (lo + hi) >> 1; if (shT[m] < v) lo = m + 1; else hi = m; }
            for (int h = 0; h < H; ++h)
                out[(size_t)h * plane + rowbase + t] = fmaf(shA[lo * H + h], v, shC[lo * H + h]);
        }
    }
}

// ---- generic fallback (runtime H, W) -------------------------------------
__global__ void fire_generic(const float* __restrict__ w1, const float* __restrict__ b1,
                             const float* __restrict__ w2, const float* __restrict__ b2,
                             const float* __restrict__ cp, const float* __restrict__ Lm,
                             const float* __restrict__ iL,
                             float* __restrict__ out, int S, int W, int H) {
    int s = blockIdx.y;
    int t = blockIdx.x * blockDim.x + threadIdx.x;
    if (t >= S) return;
    float c = cp[0];
    float thr = fabsf(Lm[0] * iL[0]);
    int d = (s >= t) ? (s - t) : (t - s);
    float log_rel = logf(fmaf((float)d + FIRE_EPS, c, FIRE_LOG_BIAS + FIRE_EPS));
    float posn = fmaxf((float)s, thr) + FIRE_EPS;
    float nd = log_rel / logf(fabsf(c * posn) + FIRE_LOG_BIAS + FIRE_EPS);
    for (int h = 0; h < H; ++h) {
        float acc = b2[h];
        for (int w = 0; w < W; ++w) {
            float hv = fmaf(w1[w], nd, b1[w]);
            hv = fmaxf(hv, 0.0f);
            acc = fmaf(w2[h * W + w], hv, acc);
        }
        out[(size_t)h * S * S + (size_t)s * S + t] = acc;
    }
}

extern "C" void kernel_launch(void* const* d_in, const int* in_sizes, int n_in,
                              void* d_out, int out_size) {
    // inputs: x, w1, b1, w2, b2, c, L_multiplier, init_L  (x unused by the math)
    const float* w1 = (const float*)d_in[1];
    const float* b1 = (const float*)d_in[2];
    const float* w2 = (const float*)d_in[3];
    const float* b2 = (const float*)d_in[4];
    const float* c  = (const float*)d_in[5];
    const float* Lm = (const float*)d_in[6];
    const float* iL = (const float*)d_in[7];

    int W = in_sizes[1];          // w1 is (W,1)
    int H = in_sizes[4];          // b2 is (H,)
    long long ss = (long long)out_size / (long long)H;  // S*S
    int S = (int)(sqrt((double)ss) + 0.5);

    fire_setup<<<8, 256>>>(w1, b1, w2, b2, c, Lm, iL, S, W, H);

    if (H == 12 && W == 32) {
        dim3 block(256);
        dim3 grid((unsigned)((S + 1023) / 1024), (unsigned)S);
        fire_main<12, 32><<<grid, block>>>((float*)d_out, S);
    } else {
        dim3 block(256);
        dim3 grid((unsigned)((S + 255) / 256), (unsigned)S);
        fire_generic<<<grid, block>>>(w1, b1, w2, b2, c, Lm, iL, (float*)d_out, S, W, H);
    }
}